// round 6
// baseline (speedup 1.0000x reference)
#include <cuda_runtime.h>
#include <cstddef>

// Problem constants (fixed by the reference)
#define BB 8
#define DD 32
#define NPIX 262144          // 512*512
#define KK 16

// Pass-1 tiling: 128 pixel-chunks x 2 d-groups x 8 images = 2048 blocks
#define P1_CHUNK  2048
#define P1_NCH    (NPIX / P1_CHUNK)   // 128

// Pass-2 tiling: one float4 (4 pixels) per thread
#define P2_TPB    256
#define P2_BLOCKS (NPIX / 4 / P2_TPB)  // 256 blocks per image

// Scratch (no cudaMalloc allowed). Fully overwritten each launch -> no zeroing.
__device__ float4 g_part2[BB * P1_NCH * 8 * KK];  // [b][chunk][pg][k] (pg = dg*4+w)
__device__ float  g_cntp[BB * P1_NCH * KK];       // per-chunk label counts
__device__ float  g_counts[BB * KK];
__device__ float  g_means[BB * KK * DD];

// ---------------------------------------------------------------------------
// Pass 1: per-image, per-chunk partial segment sums.
// Block = 128 threads = 4 warps; warp w owns planes {d0, d0+4, d0+8, d0+12},
// d0 = dg*16 + w, over a 2048-px chunk. Bins are float4 (one comp per plane):
// one label -> LDS.128 + 4 FADD + STS.128 covering FOUR values.
// Per-lane privatized bins, conflict-free (phase addr = lane*16 mod 128).
// ---------------------------------------------------------------------------
__global__ __launch_bounds__(128) void k_pass1(const float* __restrict__ emb,
                                               const int* __restrict__ gt,
                                               float* out) {
    __shared__ float4 acc4[4 * KK * 32];         // [w][k][lane]  32 KB
    __shared__ float  cnt[KK * 32];              //                2 KB
    __shared__ uchar4 lab4[P1_CHUNK / 4];        //                2 KB

    const int b  = blockIdx.z;
    const int dg = blockIdx.y;                   // d group: 0 or 1
    const int c  = blockIdx.x;                   // chunk
    const int tid = threadIdx.x;
    const int w   = tid >> 5;
    const int lane = tid & 31;

    if (b == 0 && dg == 0 && c == 0 && tid == 0) out[0] = 0.0f;

    const float4 z4 = make_float4(0.f, 0.f, 0.f, 0.f);
    #pragma unroll
    for (int j = 0; j < 16; j++) acc4[j * 128 + tid] = z4;
    #pragma unroll
    for (int j = 0; j < 4; j++) cnt[j * 128 + tid] = 0.0f;

    // Stage labels (int4 -> uchar4): 512 entries
    const int4* g4 = (const int4*)(gt + (size_t)b * NPIX + c * P1_CHUNK);
    #pragma unroll
    for (int j = 0; j < 4; j++) {
        int4 t = g4[j * 128 + tid];
        lab4[j * 128 + tid] = make_uchar4((unsigned char)t.x, (unsigned char)t.y,
                                          (unsigned char)t.z, (unsigned char)t.w);
    }
    __syncthreads();

    const int d0 = dg * 16 + w;
    const float4* eb = (const float4*)(emb + ((size_t)(b * DD + d0)) * NPIX)
                       + c * (P1_CHUNK / 4);
    const bool docnt = (dg == 0) && (w == 0);

    float4* aw = acc4 + (w * KK) * 32 + lane;
    float*  cw = cnt + lane;

    #define RMW4(K, A, B, C, D) do {                                   \
        float4 t_ = aw[(int)(K) * 32];                                  \
        t_.x += (A); t_.y += (B); t_.z += (C); t_.w += (D);             \
        aw[(int)(K) * 32] = t_;                                         \
    } while (0)

    // 512 float4 pixel-groups per chunk; lane does 16, two per iteration.
    #pragma unroll 1
    for (int i = 0; i < 8; i++) {
        const int idx = i * 64 + lane;
        float4 va = __ldcs(eb + idx);                       // plane d0
        float4 vb = __ldcs(eb + NPIX + idx);                // plane d0+4
        float4 vc = __ldcs(eb + 2 * NPIX + idx);            // plane d0+8
        float4 vd = __ldcs(eb + 3 * NPIX + idx);            // plane d0+12
        float4 ua = __ldcs(eb + idx + 32);
        float4 ub = __ldcs(eb + NPIX + idx + 32);
        float4 uc = __ldcs(eb + 2 * NPIX + idx + 32);
        float4 ud = __ldcs(eb + 3 * NPIX + idx + 32);
        uchar4 ka = lab4[idx];
        uchar4 kb = lab4[idx + 32];

        RMW4(ka.x, va.x, vb.x, vc.x, vd.x);
        RMW4(ka.y, va.y, vb.y, vc.y, vd.y);
        RMW4(ka.z, va.z, vb.z, vc.z, vd.z);
        RMW4(ka.w, va.w, vb.w, vc.w, vd.w);
        RMW4(kb.x, ua.x, ub.x, uc.x, ud.x);
        RMW4(kb.y, ua.y, ub.y, uc.y, ud.y);
        RMW4(kb.z, ua.z, ub.z, uc.z, ud.z);
        RMW4(kb.w, ua.w, ub.w, uc.w, ud.w);

        if (docnt) {
            cw[(int)ka.x * 32] += 1.0f;
            cw[(int)ka.y * 32] += 1.0f;
            cw[(int)ka.z * 32] += 1.0f;
            cw[(int)ka.w * 32] += 1.0f;
            cw[(int)kb.x * 32] += 1.0f;
            cw[(int)kb.y * 32] += 1.0f;
            cw[(int)kb.z * 32] += 1.0f;
            cw[(int)kb.w * 32] += 1.0f;
        }
    }
    #undef RMW4
    __syncwarp();

    // In-smem tree reduce: 32 lane-slots -> slot 0, for each of the 16 k rows.
    // Conflict-free: per step, phase addresses are s*16 mod 128, s distinct.
    float4* base = acc4 + (w * KK) * 32;
    for (int it = lane; it < 256; it += 32) {        // off = 16
        int k = it >> 4, s = it & 15;
        float4* r = base + k * 32;
        float4 x = r[s], y = r[s + 16];
        x.x += y.x; x.y += y.y; x.z += y.z; x.w += y.w;
        r[s] = x;
    }
    __syncwarp();
    for (int it = lane; it < 128; it += 32) {        // off = 8
        int k = it >> 3, s = it & 7;
        float4* r = base + k * 32;
        float4 x = r[s], y = r[s + 8];
        x.x += y.x; x.y += y.y; x.z += y.z; x.w += y.w;
        r[s] = x;
    }
    __syncwarp();
    for (int it = lane; it < 64; it += 32) {         // off = 4
        int k = it >> 2, s = it & 3;
        float4* r = base + k * 32;
        float4 x = r[s], y = r[s + 4];
        x.x += y.x; x.y += y.y; x.z += y.z; x.w += y.w;
        r[s] = x;
    }
    __syncwarp();
    {                                                // off = 2 (all 32 lanes)
        int k = lane >> 1, s = lane & 1;
        float4* r = base + k * 32;
        float4 x = r[s], y = r[s + 2];
        x.x += y.x; x.y += y.y; x.z += y.z; x.w += y.w;
        r[s] = x;
    }
    __syncwarp();
    if (lane < 16) {                                 // off = 1 + store
        float4* r = base + lane * 32;
        float4 x = r[0], y = r[1];
        x.x += y.x; x.y += y.y; x.z += y.z; x.w += y.w;
        g_part2[((b * P1_NCH + c) * 8 + (dg * 4 + w)) * KK + lane] = x;
    }

    if (docnt) {
        __syncwarp();
        for (int it = lane; it < 256; it += 32) {
            int k = it >> 4, s = it & 15;
            cnt[k * 32 + s] += cnt[k * 32 + s + 16];
        }
        __syncwarp();
        for (int it = lane; it < 128; it += 32) {
            int k = it >> 3, s = it & 7;
            cnt[k * 32 + s] += cnt[k * 32 + s + 8];
        }
        __syncwarp();
        for (int it = lane; it < 64; it += 32) {
            int k = it >> 2, s = it & 3;
            cnt[k * 32 + s] += cnt[k * 32 + s + 4];
        }
        __syncwarp();
        {
            int k = lane >> 1, s = lane & 1;
            cnt[k * 32 + s] += cnt[k * 32 + s + 2];
        }
        __syncwarp();
        if (lane < 16)
            g_cntp[(b * P1_NCH + c) * KK + lane] = cnt[lane * 32] + cnt[lane * 32 + 1];
    }
}

// ---------------------------------------------------------------------------
// Finalize: reduce partials -> counts & means; pairwise push loss; reg loss.
// One block per image.
// ---------------------------------------------------------------------------
__global__ __launch_bounds__(256) void k_finalize(float* out) {
    __shared__ float m[KK * 33];    // padded means
    __shared__ float cs[KK];
    __shared__ float red[256];

    const int b = blockIdx.x;
    const int tid = threadIdx.x;

    if (tid < KK) {
        float s = 0.0f;
        #pragma unroll 4
        for (int c = 0; c < P1_NCH; c++)
            s += g_cntp[(b * P1_NCH + c) * KK + tid];
        float cv = fmaxf(s, 1.0f);
        cs[tid] = cv;
        g_counts[b * KK + tid] = cv;
    }
    __syncthreads();

    if (tid < 128) {
        const int pg = tid >> 4;           // plane group: dg*4 + w
        const int k  = tid & 15;
        float4 s = make_float4(0.f, 0.f, 0.f, 0.f);
        #pragma unroll 4
        for (int c = 0; c < P1_NCH; c++) {
            float4 t = g_part2[((b * P1_NCH + c) * 8 + pg) * KK + k];
            s.x += t.x; s.y += t.y; s.z += t.z; s.w += t.w;
        }
        const int dgv = pg >> 2, wv = pg & 3;
        const int dbase = dgv * 16 + wv;
        const float inv = 1.0f / cs[k];
        float m0 = s.x * inv, m1 = s.y * inv, m2 = s.z * inv, m3 = s.w * inv;
        m[k * 33 + dbase]      = m0;
        m[k * 33 + dbase + 4]  = m1;
        m[k * 33 + dbase + 8]  = m2;
        m[k * 33 + dbase + 12] = m3;
        g_means[(b * KK + k) * DD + dbase]      = m0;
        g_means[(b * KK + k) * DD + dbase + 4]  = m1;
        g_means[(b * KK + k) * DD + dbase + 8]  = m2;
        g_means[(b * KK + k) * DD + dbase + 12] = m3;
    }
    __syncthreads();

    // Pairwise hinge on cluster-mean distances: thread -> (i,j), upper tri only.
    const int i = tid >> 4;
    const int j = tid & 15;
    float contrib = 0.0f;
    if (j > i) {
        float d2 = 0.0f;
        #pragma unroll
        for (int d = 0; d < DD; d++) {
            float df = m[i * 33 + d] - m[j * 33 + d];
            d2 = fmaf(df, df, d2);
        }
        float pd = sqrtf(d2);             // i<j: diagonal eye irrelevant
        float h = fmaxf(3.0f - pd, 0.0f); // 2 * DIST_THETA = 3.0
        contrib = h * h;
    }

    float reg = 0.0f;
    if (tid < KK) {
        float n2 = 0.0f;
        #pragma unroll
        for (int d = 0; d < DD; d++) {
            float v = m[tid * 33 + d];
            n2 = fmaf(v, v, n2);
        }
        reg = sqrtf(n2);
    }

    red[tid] = contrib * (1.0f / (KK * (KK - 1))) + 0.001f * reg * (1.0f / KK);
    __syncthreads();
    for (int off = 128; off; off >>= 1) {
        if (tid < off) red[tid] += red[tid + off];
        __syncthreads();
    }
    if (tid == 0) atomicAdd(out, red[0] * (1.0f / BB));
}

// ---------------------------------------------------------------------------
// Pass 2: per-pixel hinge variance loss, folded directly into the scalar.
// One float4 (4 consecutive pixels) per thread; batched LDG.128s.
// ---------------------------------------------------------------------------
__global__ __launch_bounds__(P2_TPB) void k_pass2(const float* __restrict__ emb,
                                                  const int* __restrict__ gt,
                                                  float* out) {
    __shared__ float m[KK * 33];
    __shared__ float wk[KK];
    __shared__ float red[P2_TPB / 32];

    const int b  = blockIdx.y;
    const int tid = threadIdx.x;
    const int lane = tid & 31;
    const int w = tid >> 5;
    const int p4 = blockIdx.x * P2_TPB + tid;    // float4 index

    for (int j = tid; j < KK * DD; j += P2_TPB)
        m[(j / DD) * 33 + (j % DD)] = g_means[b * KK * DD + j];
    if (tid < KK)
        wk[tid] = 1.0f / ((float)KK * fmaxf(g_counts[b * KK + tid], 1.0f));
    __syncthreads();

    const float4* e4 = (const float4*)(emb + (size_t)b * DD * NPIX);
    const int4 kk = ((const int4*)(gt + (size_t)b * NPIX))[p4];

    const float* m0 = m + kk.x * 33;
    const float* m1 = m + kk.y * 33;
    const float* m2 = m + kk.z * 33;
    const float* m3 = m + kk.w * 33;

    float a0 = 0.0f, a1 = 0.0f, a2 = 0.0f, a3 = 0.0f;
    #pragma unroll
    for (int g = 0; g < 4; g++) {
        float4 v[8];
        #pragma unroll
        for (int j = 0; j < 8; j++)
            v[j] = __ldcs(&e4[(size_t)(g * 8 + j) * (NPIX / 4) + p4]);
        #pragma unroll
        for (int j = 0; j < 8; j++) {
            const int d = g * 8 + j;
            float t;
            t = v[j].x - m0[d]; a0 = fmaf(t, t, a0);
            t = v[j].y - m1[d]; a1 = fmaf(t, t, a1);
            t = v[j].z - m2[d]; a2 = fmaf(t, t, a2);
            t = v[j].w - m3[d]; a3 = fmaf(t, t, a3);
        }
    }

    float h, lacc = 0.0f;
    h = fmaxf(sqrtf(a0) - 0.5f, 0.0f); lacc = fmaf(h * h, wk[kk.x], lacc);
    h = fmaxf(sqrtf(a1) - 0.5f, 0.0f); lacc = fmaf(h * h, wk[kk.y], lacc);
    h = fmaxf(sqrtf(a2) - 0.5f, 0.0f); lacc = fmaf(h * h, wk[kk.z], lacc);
    h = fmaxf(sqrtf(a3) - 0.5f, 0.0f); lacc = fmaf(h * h, wk[kk.w], lacc);

    #pragma unroll
    for (int off = 16; off; off >>= 1)
        lacc += __shfl_down_sync(0xffffffffu, lacc, off);
    if (lane == 0) red[w] = lacc;
    __syncthreads();
    if (tid == 0) {
        float s = 0.0f;
        #pragma unroll
        for (int i = 0; i < P2_TPB / 32; i++) s += red[i];
        atomicAdd(out, s * (1.0f / BB));
    }
}

// ---------------------------------------------------------------------------
extern "C" void kernel_launch(void* const* d_in, const int* in_sizes, int n_in,
                              void* d_out, int out_size) {
    int ei = 0, gi = 1;
    // Defensive: identify inputs by size (embeddings = 67108864, gt = 2097152)
    if (n_in >= 2 && in_sizes[0] == BB * NPIX) { ei = 1; gi = 0; }

    const float* emb = (const float*)d_in[ei];
    const int*   gt  = (const int*)d_in[gi];
    float* out = (float*)d_out;

    k_pass1<<<dim3(P1_NCH, 2, BB), 128>>>(emb, gt, out);
    k_finalize<<<BB, 256>>>(out);
    k_pass2<<<dim3(P2_BLOCKS, BB), P2_TPB>>>(emb, gt, out);
}